// round 4
// baseline (speedup 1.0000x reference)
#include <cuda_runtime.h>
#include <math.h>

// Problem shape (fixed by the reference)
#define BATCH 2
#define SEQ 2048
#define DMODEL 2048
#define NH 32
#define NKV 8
#define HD 64
#define KVD (NKV * HD)        // 512
#define MROWS (BATCH * SEQ)   // 4096

// Scratch (no cudaMalloc allowed) — ~84 MB total
static __device__ float g_Q[(size_t)MROWS * DMODEL];
static __device__ float g_K[(size_t)MROWS * KVD];
static __device__ float g_V[(size_t)MROWS * KVD];
static __device__ float g_A[(size_t)MROWS * DMODEL];

// Swizzle for [rows][32] fp32 tiles, XOR keyed on (row>>3):
//  - cooperative STS.128: 8 lanes per row, c4 covers all 32 banks  -> clean
//  - A-fragment reads (same row per half-warp): broadcast          -> clean
//  - B-fragment reads (rows strided by 8): c = k4 ^ ((tx&7)<<2),
//    8 distinct slots, lanes L and L+16 read identical addresses   -> clean
__device__ __forceinline__ int swz8(int row, int col4base) {
    return (row << 5) + (col4base ^ (((row >> 3) & 7) << 2));
}

// ---------------------------------------------------------------------------
// C[M,N] = A[M,K] @ W[N,K]^T   (both operands K-major, row-major storage)
// 128x128 C tile, BK=32, 256 threads, 8x8 microtile, rank-4 float4 updates,
// register-prefetch pipeline on the global tile loads (32 KB static smem).
// ---------------------------------------------------------------------------
__global__ __launch_bounds__(256) void gemm_nt_kernel(
    const float* __restrict__ A, const float* __restrict__ W,
    float* __restrict__ C, int M, int N, int K)
{
    __shared__ float As[128 * 32];   // 16 KB
    __shared__ float Bs[128 * 32];   // 16 KB

    const int tid = threadIdx.x;
    const int tx = tid & 15;          // 0..15 -> C cols (8 each)
    const int ty = tid >> 4;          // 0..15 -> C rows (8 each)
    const int m0 = blockIdx.y * 128;
    const int n0 = blockIdx.x * 128;

    // Per-thread cooperative-load coordinates (fixed across k-iterations)
    const int lrow = tid >> 3;            // 0..31 base row (+32*it)
    const int lc4  = (tid & 7) << 2;      // 0,4,...,28

    float acc[8][8];
#pragma unroll
    for (int m = 0; m < 8; m++)
#pragma unroll
        for (int n = 0; n < 8; n++) acc[m][n] = 0.f;

    // --- prologue: tile k0=0 straight to smem ---
#pragma unroll
    for (int it = 0; it < 4; it++) {
        const int row = lrow + it * 32;
        *(float4*)&As[swz8(row, lc4)] =
            *(const float4*)&A[(size_t)(m0 + row) * K + lc4];
        *(float4*)&Bs[swz8(row, lc4)] =
            *(const float4*)&W[(size_t)(n0 + row) * K + lc4];
    }
    __syncthreads();

    for (int k0 = 0; k0 < K; k0 += 32) {
        const bool have_next = (k0 + 32) < K;

        // --- prefetch next tile into registers (overlaps with compute) ---
        float4 pa[4], pb[4];
        if (have_next) {
            const int kn = k0 + 32;
#pragma unroll
            for (int it = 0; it < 4; it++) {
                const int row = lrow + it * 32;
                pa[it] = *(const float4*)&A[(size_t)(m0 + row) * K + kn + lc4];
                pb[it] = *(const float4*)&W[(size_t)(n0 + row) * K + kn + lc4];
            }
        }

        // --- compute from smem ---
#pragma unroll
        for (int k4 = 0; k4 < 32; k4 += 4) {
            float4 av[8], bv[8];
#pragma unroll
            for (int m = 0; m < 8; m++)
                av[m] = *(const float4*)&As[swz8(ty * 8 + m, k4)];
#pragma unroll
            for (int n = 0; n < 8; n++)
                bv[n] = *(const float4*)&Bs[swz8(tx * 8 + n, k4)];
#pragma unroll
            for (int m = 0; m < 8; m++)
#pragma unroll
                for (int n = 0; n < 8; n++)
                    acc[m][n] += av[m].x * bv[n].x + av[m].y * bv[n].y +
                                 av[m].z * bv[n].z + av[m].w * bv[n].w;
        }
        __syncthreads();

        // --- commit prefetched tile to smem ---
        if (have_next) {
#pragma unroll
            for (int it = 0; it < 4; it++) {
                *(float4*)&As[swz8(lrow + it * 32, lc4)] = pa[it];
                *(float4*)&Bs[swz8(lrow + it * 32, lc4)] = pb[it];
            }
            __syncthreads();
        }
    }

#pragma unroll
    for (int m = 0; m < 8; m++) {
        float* crow = &C[(size_t)(m0 + ty * 8 + m) * N + n0 + tx * 8];
        *(float4*)crow       = make_float4(acc[m][0], acc[m][1], acc[m][2], acc[m][3]);
        *(float4*)(crow + 4) = make_float4(acc[m][4], acc[m][5], acc[m][6], acc[m][7]);
    }
}

// ---------------------------------------------------------------------------
// Causal GQA flash attention.
// Grid: (SEQ/128, NH, BATCH). 256 threads; 2 threads per query row, each
// owning one 32-wide half of the head dim. BN=32 K/V tiles in smem.
// Q layout: [B*T, NH*HD] (row = token). K/V layout: [B*T, NKV*HD].
// ---------------------------------------------------------------------------
__global__ __launch_bounds__(256) void attn_kernel(
    const float* __restrict__ Q, const float* __restrict__ K,
    const float* __restrict__ V, float* __restrict__ O)
{
    __shared__ float Ks[32][64];
    __shared__ float Vs[32][64];

    const int qt   = blockIdx.x;
    const int h    = blockIdx.y;
    const int b    = blockIdx.z;
    const int hk   = h >> 2;                 // GQA ratio 4
    const int tid  = threadIdx.x;
    const int r    = tid >> 1;               // 0..127 query row in tile
    const int half = tid & 1;                // head-dim half
    const int qrow = qt * 128 + r;           // global query position
    const float scale = 0.125f;              // 1/sqrt(64)
    const float NEG_INF = -__int_as_float(0x7f800000);

    // Query row half into registers
    float q[32];
    {
        const float* qp = Q + ((size_t)(b * SEQ + qrow)) * DMODEL + h * HD + half * 32;
#pragma unroll
        for (int i = 0; i < 32; i += 4) {
            const float4 v4 = *(const float4*)(qp + i);
            q[i] = v4.x; q[i + 1] = v4.y; q[i + 2] = v4.z; q[i + 3] = v4.w;
        }
    }

    float acc[32];
#pragma unroll
    for (int i = 0; i < 32; i++) acc[i] = 0.f;
    float mval = NEG_INF;
    float lsum = 0.f;

    const int kv_end = qt * 128 + 128;       // causal upper bound for this tile
    for (int j0 = 0; j0 < kv_end; j0 += 32) {
        // Cooperative K/V tile load: 32 rows x 64 floats each.
#pragma unroll
        for (int it = 0; it < 2; it++) {
            const int idx = tid + it * 256;          // 0..511 float4 ids
            const int row = idx >> 4;                // 0..31
            const int c4  = (idx & 15) << 2;         // 0..60
            const size_t gro = ((size_t)(b * SEQ + j0 + row)) * KVD + hk * HD + c4;
            *(float4*)&Ks[row][c4] = *(const float4*)&K[gro];
            *(float4*)&Vs[row][c4] = *(const float4*)&V[gro];
        }
        __syncthreads();

        const bool masked_tile = (j0 + 31 > qrow);   // only diagonal tiles mask

        // Scores for 32 keys (pair-sum over the two head-dim halves)
        float s[32];
        float tmax = NEG_INF;
#pragma unroll
        for (int j = 0; j < 32; j++) {
            float p = 0.f;
#pragma unroll
            for (int kk = 0; kk < 32; kk += 4) {
                const float4 kv4 = *(const float4*)&Ks[j][half * 32 + kk];
                p += q[kk] * kv4.x + q[kk + 1] * kv4.y +
                     q[kk + 2] * kv4.z + q[kk + 3] * kv4.w;
            }
            p += __shfl_xor_sync(0xffffffffu, p, 1);  // full 64-dim dot
            p *= scale;
            if (masked_tile && (j0 + j > qrow)) p = NEG_INF;
            s[j] = p;
            tmax = fmaxf(tmax, p);
        }

        // Online softmax rescale
        const float mnew = fmaxf(mval, tmax);
        const float corr = __expf(mval - mnew);        // 0 when mval==-inf
        lsum *= corr;
#pragma unroll
        for (int kk = 0; kk < 32; kk++) acc[kk] *= corr;

        // P @ V accumulate
#pragma unroll
        for (int j = 0; j < 32; j++) {
            const float p = __expf(s[j] - mnew);
            lsum += p;
#pragma unroll
            for (int kk = 0; kk < 32; kk += 4) {
                const float4 v4 = *(const float4*)&Vs[j][half * 32 + kk];
                acc[kk]     += p * v4.x;
                acc[kk + 1] += p * v4.y;
                acc[kk + 2] += p * v4.z;
                acc[kk + 3] += p * v4.w;
            }
        }
        mval = mnew;
        __syncthreads();
    }

    const float inv = 1.f / lsum;
    float* op = O + ((size_t)(b * SEQ + qrow)) * DMODEL + h * HD + half * 32;
#pragma unroll
    for (int kk = 0; kk < 32; kk += 4) {
        const float4 v4 = make_float4(acc[kk] * inv, acc[kk + 1] * inv,
                                      acc[kk + 2] * inv, acc[kk + 3] * inv);
        *(float4*)(op + kk) = v4;
    }
}

// ---------------------------------------------------------------------------
extern "C" void kernel_launch(void* const* d_in, const int* in_sizes, int n_in,
                              void* d_out, int out_size)
{
    const float* x  = (const float*)d_in[0];
    const float* wq = (const float*)d_in[1];
    const float* wk = (const float*)d_in[2];
    const float* wv = (const float*)d_in[3];
    const float* wo = (const float*)d_in[4];
    float* out = (float*)d_out;

    float *Qp, *Kp, *Vp, *Ap;
    cudaGetSymbolAddress((void**)&Qp, g_Q);
    cudaGetSymbolAddress((void**)&Kp, g_K);
    cudaGetSymbolAddress((void**)&Vp, g_V);
    cudaGetSymbolAddress((void**)&Ap, g_A);

    // Projections: Q = x @ wq^T, K = x @ wk^T, V = x @ wv^T
    gemm_nt_kernel<<<dim3(DMODEL / 128, MROWS / 128), 256>>>(x, wq, Qp, MROWS, DMODEL, DMODEL);
    gemm_nt_kernel<<<dim3(KVD / 128,    MROWS / 128), 256>>>(x, wk, Kp, MROWS, KVD,    DMODEL);
    gemm_nt_kernel<<<dim3(KVD / 128,    MROWS / 128), 256>>>(x, wv, Vp, MROWS, KVD,    DMODEL);

    // Causal GQA attention -> g_A in [B*T, NH*HD] layout
    attn_kernel<<<dim3(SEQ / 128, NH, BATCH), 256>>>(Qp, Kp, Vp, Ap);

    // Output projection: out = A @ wo^T
    gemm_nt_kernel<<<dim3(DMODEL / 128, MROWS / 128), 256>>>(Ap, wo, out, MROWS, DMODEL, DMODEL);
}

// round 6
// speedup vs baseline: 1.5348x; 1.5348x over previous
#include <cuda_runtime.h>
#include <math.h>
#include <stdint.h>

// Problem shape (fixed by the reference)
#define BATCH 2
#define SEQ 2048
#define DMODEL 2048
#define NH 32
#define NKV 8
#define HD 64
#define KVD (NKV * HD)        // 512
#define MROWS (BATCH * SEQ)   // 4096

// Scratch (no cudaMalloc allowed) — ~84 MB total
static __device__ float g_Q[(size_t)MROWS * DMODEL];
static __device__ float g_K[(size_t)MROWS * KVD];
static __device__ float g_V[(size_t)MROWS * KVD];
static __device__ float g_A[(size_t)MROWS * DMODEL];

// ---------------------------------------------------------------------------
// tf32 helpers
// ---------------------------------------------------------------------------
__device__ __forceinline__ uint32_t f2tf32(float x) {
    uint32_t u;
    asm("cvt.rna.tf32.f32 %0, %1;" : "=r"(u) : "r"(__float_as_uint(x)));
    return u;
}

__device__ __forceinline__ void mma_tf32(float c[4],
                                         uint32_t a0, uint32_t a1,
                                         uint32_t a2, uint32_t a3,
                                         uint32_t b0, uint32_t b1) {
    asm volatile(
        "mma.sync.aligned.m16n8k8.row.col.f32.tf32.tf32.f32 "
        "{%0,%1,%2,%3}, {%4,%5,%6,%7}, {%8,%9}, {%0,%1,%2,%3};"
        : "+f"(c[0]), "+f"(c[1]), "+f"(c[2]), "+f"(c[3])
        : "r"(a0), "r"(a1), "r"(a2), "r"(a3), "r"(b0), "r"(b1));
}

// GEMM smem swizzle: float index = row*32 + (col ^ (8*(row&3))).
// XOR value is a multiple of 8 -> preserves float4 (stores) and float2 (frag
// reads) alignment. Phase analysis: frag LDS.64 banks = 8*(ks^g)+2t (16
// distinct per half-warp phase); STS.128 covers all 32 banks per 8-lane phase.
__device__ __forceinline__ int gswz(int row, int col) {
    return (row << 5) + (col ^ ((row & 3) << 3));
}

// ---------------------------------------------------------------------------
// C[M,N] = A[M,K] @ W[N,K]^T  via tf32 mma.sync.m16n8k8.
// CTA: 256 threads (8 warps, 4x2), C tile 128x128; warp tile 32x64.
// BK=32 (4 k8-steps). K-slot permutation: mma slot t <-> k=2t, t+4 <-> 2t+1,
// applied identically to A and B, so every fragment load is one LDS.64.
// fp32->tf32 conversion happens once, at smem-commit time.
// ---------------------------------------------------------------------------
__global__ __launch_bounds__(256) void gemm_nt_tc_kernel(
    const float* __restrict__ A, const float* __restrict__ W,
    float* __restrict__ C, int M, int N, int K)
{
    __shared__ uint32_t As[128 * 32];   // 16 KB, tf32 bits
    __shared__ uint32_t Bs[128 * 32];   // 16 KB

    const int tid  = threadIdx.x;
    const int lane = tid & 31;
    const int warp = tid >> 5;
    const int wm   = warp >> 1;          // 0..3 -> 32-row band
    const int wn   = warp & 1;           // 0..1 -> 64-col band
    const int g    = lane >> 2;          // mma group id (0..7)
    const int t    = lane & 3;           // thread-in-group

    const int m0 = blockIdx.y * 128;
    const int n0 = blockIdx.x * 128;

    // Cooperative-load coordinates
    const int lrow = tid >> 3;            // 0..31 (+32*it)
    const int lc4  = (tid & 7) << 2;      // 0,4,...,28

    float acc[2][8][4];
#pragma unroll
    for (int mt = 0; mt < 2; mt++)
#pragma unroll
        for (int nt = 0; nt < 8; nt++)
#pragma unroll
            for (int i = 0; i < 4; i++) acc[mt][nt][i] = 0.f;

    // --- prologue: tile k0=0 -> cvt -> smem ---
#pragma unroll
    for (int it = 0; it < 4; it++) {
        const int row = lrow + it * 32;
        const float4 va = *(const float4*)&A[(size_t)(m0 + row) * K + lc4];
        const float4 vb = *(const float4*)&W[(size_t)(n0 + row) * K + lc4];
        uint32_t* da = &As[gswz(row, lc4)];
        uint32_t* db = &Bs[gswz(row, lc4)];
        da[0] = f2tf32(va.x); da[1] = f2tf32(va.y);
        da[2] = f2tf32(va.z); da[3] = f2tf32(va.w);
        db[0] = f2tf32(vb.x); db[1] = f2tf32(vb.y);
        db[2] = f2tf32(vb.z); db[3] = f2tf32(vb.w);
    }
    __syncthreads();

    for (int k0 = 0; k0 < K; k0 += 32) {
        const bool have_next = (k0 + 32) < K;

        // --- prefetch next tile into registers (overlaps the mma block) ---
        float4 pa[4], pb[4];
        if (have_next) {
            const int kn = k0 + 32;
#pragma unroll
            for (int it = 0; it < 4; it++) {
                const int row = lrow + it * 32;
                pa[it] = *(const float4*)&A[(size_t)(m0 + row) * K + kn + lc4];
                pb[it] = *(const float4*)&W[(size_t)(n0 + row) * K + kn + lc4];
            }
        }

        // --- 4 k8-steps of mma from smem ---
#pragma unroll
        for (int ks = 0; ks < 4; ks++) {
            const int kb = ks * 8 + 2 * t;   // permuted k-slot base for this lane

            uint2 af[2][2];                  // [mt][row-half]: .x=slot t, .y=slot t+4
#pragma unroll
            for (int mt = 0; mt < 2; mt++) {
                const int ra = wm * 32 + mt * 16 + g;
                af[mt][0] = *(const uint2*)&As[gswz(ra,     kb)];
                af[mt][1] = *(const uint2*)&As[gswz(ra + 8, kb)];
            }
            uint2 bf[8];
#pragma unroll
            for (int nt = 0; nt < 8; nt++) {
                const int rb = wn * 64 + nt * 8 + g;
                bf[nt] = *(const uint2*)&Bs[gswz(rb, kb)];
            }
#pragma unroll
            for (int mt = 0; mt < 2; mt++)
#pragma unroll
                for (int nt = 0; nt < 8; nt++)
                    mma_tf32(acc[mt][nt],
                             af[mt][0].x, af[mt][1].x,   // a0, a1
                             af[mt][0].y, af[mt][1].y,   // a2, a3
                             bf[nt].x, bf[nt].y);
        }
        __syncthreads();

        // --- commit prefetched tile (cvt at store) ---
        if (have_next) {
#pragma unroll
            for (int it = 0; it < 4; it++) {
                const int row = lrow + it * 32;
                uint32_t* da = &As[gswz(row, lc4)];
                uint32_t* db = &Bs[gswz(row, lc4)];
                da[0] = f2tf32(pa[it].x); da[1] = f2tf32(pa[it].y);
                da[2] = f2tf32(pa[it].z); da[3] = f2tf32(pa[it].w);
                db[0] = f2tf32(pb[it].x); db[1] = f2tf32(pb[it].y);
                db[2] = f2tf32(pb[it].z); db[3] = f2tf32(pb[it].w);
            }
            __syncthreads();
        }
    }

    // --- epilogue: c0/c1 at (row, 2t), c2/c3 at (row+8, 2t) ---
#pragma unroll
    for (int mt = 0; mt < 2; mt++) {
        const int row = m0 + wm * 32 + mt * 16 + g;
#pragma unroll
        for (int nt = 0; nt < 8; nt++) {
            const int col = n0 + wn * 64 + nt * 8 + 2 * t;
            *(float2*)&C[(size_t)row * N + col] =
                make_float2(acc[mt][nt][0], acc[mt][nt][1]);
            *(float2*)&C[(size_t)(row + 8) * N + col] =
                make_float2(acc[mt][nt][2], acc[mt][nt][3]);
        }
    }
}

// ---------------------------------------------------------------------------
// Causal GQA flash attention, register-tiled:
// each thread owns 2 query rows x one 16-wide head-dim quarter.
// Grid: (SEQ/128, NH, BATCH), 256 threads (64 row-pairs x 4 quarters).
// ---------------------------------------------------------------------------
__global__ __launch_bounds__(256) void attn_kernel(
    const float* __restrict__ Q, const float* __restrict__ K,
    const float* __restrict__ V, float* __restrict__ O)
{
    __shared__ float Ks[32][64];
    __shared__ float Vs[32][64];

    const int qt   = blockIdx.x;
    const int h    = blockIdx.y;
    const int b    = blockIdx.z;
    const int hk   = h >> 2;                 // GQA ratio 4
    const int tid  = threadIdx.x;
    const int q4   = tid & 3;                // head-dim quarter (16 floats)
    const int rp   = tid >> 2;               // 0..63 row pair
    const int qrow0 = qt * 128 + rp * 2;
    const int qrow1 = qrow0 + 1;
    const float scale = 0.125f;              // 1/sqrt(64)
    const float NEG_INF = -__int_as_float(0x7f800000);

    float qa[16], qb[16];
    {
        const float* qp0 = Q + ((size_t)(b * SEQ + qrow0)) * DMODEL + h * HD + q4 * 16;
        const float* qp1 = qp0 + DMODEL;
#pragma unroll
        for (int i = 0; i < 16; i += 4) {
            float4 v0 = *(const float4*)(qp0 + i);
            float4 v1 = *(const float4*)(qp1 + i);
            qa[i] = v0.x; qa[i+1] = v0.y; qa[i+2] = v0.z; qa[i+3] = v0.w;
            qb[i] = v1.x; qb[i+1] = v1.y; qb[i+2] = v1.z; qb[i+3] = v1.w;
        }
    }

    float aa[16], ab[16];
#pragma unroll
    for (int i = 0; i < 16; i++) { aa[i] = 0.f; ab[i] = 0.f; }
    float m0v = NEG_INF, m1v = NEG_INF;
    float l0 = 0.f, l1 = 0.f;

    const int lr0 = tid >> 4;                // rows 0..15 (+16)
    const int lc4 = (tid & 15) << 2;         // 0..60

    const int kv_end = qt * 128 + 128;

    // Prologue: tile 0
#pragma unroll
    for (int it = 0; it < 2; it++) {
        const int row = lr0 + it * 16;
        const size_t gro = ((size_t)(b * SEQ + row)) * KVD + hk * HD + lc4;
        *(float4*)&Ks[row][lc4] = *(const float4*)&K[gro];
        *(float4*)&Vs[row][lc4] = *(const float4*)&V[gro];
    }
    __syncthreads();

    for (int j0 = 0; j0 < kv_end; j0 += 32) {
        const bool have_next = (j0 + 32) < kv_end;

        float4 pk[2], pv[2];
        if (have_next) {
#pragma unroll
            for (int it = 0; it < 2; it++) {
                const int row = lr0 + it * 16;
                const size_t gro = ((size_t)(b * SEQ + j0 + 32 + row)) * KVD + hk * HD + lc4;
                pk[it] = *(const float4*)&K[gro];
                pv[it] = *(const float4*)&V[gro];
            }
        }

        const bool masked_tile = (j0 + 31 > qrow0);

        float s0[32], s1[32];
        float tmax0 = NEG_INF, tmax1 = NEG_INF;
#pragma unroll
        for (int j = 0; j < 32; j++) {
            float p0 = 0.f, p1 = 0.f;
#pragma unroll
            for (int kk = 0; kk < 16; kk += 4) {
                const float4 kv4 = *(const float4*)&Ks[j][q4 * 16 + kk];
                p0 += qa[kk] * kv4.x + qa[kk+1] * kv4.y + qa[kk+2] * kv4.z + qa[kk+3] * kv4.w;
                p1 += qb[kk] * kv4.x + qb[kk+1] * kv4.y + qb[kk+2] * kv4.z + qb[kk+3] * kv4.w;
            }
            p0 += __shfl_xor_sync(0xffffffffu, p0, 1);
            p0 += __shfl_xor_sync(0xffffffffu, p0, 2);
            p1 += __shfl_xor_sync(0xffffffffu, p1, 1);
            p1 += __shfl_xor_sync(0xffffffffu, p1, 2);
            p0 *= scale;
            p1 *= scale;
            if (masked_tile) {
                if (j0 + j > qrow0) p0 = NEG_INF;
                if (j0 + j > qrow1) p1 = NEG_INF;
            }
            s0[j] = p0; s1[j] = p1;
            tmax0 = fmaxf(tmax0, p0);
            tmax1 = fmaxf(tmax1, p1);
        }

        const float mn0 = fmaxf(m0v, tmax0);
        const float mn1 = fmaxf(m1v, tmax1);
        const float c0 = __expf(m0v - mn0);
        const float c1 = __expf(m1v - mn1);
        l0 *= c0; l1 *= c1;
#pragma unroll
        for (int i = 0; i < 16; i++) { aa[i] *= c0; ab[i] *= c1; }

#pragma unroll
        for (int j = 0; j < 32; j++) {
            const float e0 = __expf(s0[j] - mn0);
            const float e1 = __expf(s1[j] - mn1);
            l0 += e0; l1 += e1;
#pragma unroll
            for (int kk = 0; kk < 16; kk += 4) {
                const float4 v4 = *(const float4*)&Vs[j][q4 * 16 + kk];
                aa[kk]   += e0 * v4.x; aa[kk+1] += e0 * v4.y;
                aa[kk+2] += e0 * v4.z; aa[kk+3] += e0 * v4.w;
                ab[kk]   += e1 * v4.x; ab[kk+1] += e1 * v4.y;
                ab[kk+2] += e1 * v4.z; ab[kk+3] += e1 * v4.w;
            }
        }
        m0v = mn0; m1v = mn1;
        __syncthreads();

        if (have_next) {
#pragma unroll
            for (int it = 0; it < 2; it++) {
                const int row = lr0 + it * 16;
                *(float4*)&Ks[row][lc4] = pk[it];
                *(float4*)&Vs[row][lc4] = pv[it];
            }
            __syncthreads();
        }
    }

    const float i0 = 1.f / l0;
    const float i1 = 1.f / l1;
    float* op0 = O + ((size_t)(b * SEQ + qrow0)) * DMODEL + h * HD + q4 * 16;
    float* op1 = op0 + DMODEL;
#pragma unroll
    for (int kk = 0; kk < 16; kk += 4) {
        *(float2*)(op0 + kk)     = make_float2(aa[kk] * i0, aa[kk+1] * i0);
        *(float2*)(op0 + kk + 2) = make_float2(aa[kk+2] * i0, aa[kk+3] * i0);
        *(float2*)(op1 + kk)     = make_float2(ab[kk] * i1, ab[kk+1] * i1);
        *(float2*)(op1 + kk + 2) = make_float2(ab[kk+2] * i1, ab[kk+3] * i1);
    }
}

// ---------------------------------------------------------------------------
extern "C" void kernel_launch(void* const* d_in, const int* in_sizes, int n_in,
                              void* d_out, int out_size)
{
    const float* x  = (const float*)d_in[0];
    const float* wq = (const float*)d_in[1];
    const float* wk = (const float*)d_in[2];
    const float* wv = (const float*)d_in[3];
    const float* wo = (const float*)d_in[4];
    float* out = (float*)d_out;

    float *Qp, *Kp, *Vp, *Ap;
    cudaGetSymbolAddress((void**)&Qp, g_Q);
    cudaGetSymbolAddress((void**)&Kp, g_K);
    cudaGetSymbolAddress((void**)&Vp, g_V);
    cudaGetSymbolAddress((void**)&Ap, g_A);

    // Projections: Q = x @ wq^T, K = x @ wk^T, V = x @ wv^T  (tf32 tensor core)
    gemm_nt_tc_kernel<<<dim3(DMODEL / 128, MROWS / 128), 256>>>(x, wq, Qp, MROWS, DMODEL, DMODEL);
    gemm_nt_tc_kernel<<<dim3(KVD / 128,    MROWS / 128), 256>>>(x, wk, Kp, MROWS, KVD,    DMODEL);
    gemm_nt_tc_kernel<<<dim3(KVD / 128,    MROWS / 128), 256>>>(x, wv, Vp, MROWS, KVD,    DMODEL);

    // Causal GQA attention -> g_A in [B*T, NH*HD] layout (fp32)
    attn_kernel<<<dim3(SEQ / 128, NH, BATCH), 256>>>(Qp, Kp, Vp, Ap);

    // Output projection: out = A @ wo^T  (tf32 tensor core)
    gemm_nt_tc_kernel<<<dim3(DMODEL / 128, MROWS / 128), 256>>>(Ap, wo, out, MROWS, DMODEL, DMODEL);
}

// round 8
// speedup vs baseline: 4.1325x; 2.6926x over previous
#include <cuda_runtime.h>
#include <math.h>
#include <stdint.h>

// Problem shape (fixed by the reference)
#define BATCH 2
#define SEQ 2048
#define DMODEL 2048
#define NH 32
#define NKV 8
#define HD 64
#define KVD (NKV * HD)        // 512
#define MROWS (BATCH * SEQ)   // 4096

// Scratch (no cudaMalloc allowed) — ~84 MB total
static __device__ float g_Q[(size_t)MROWS * DMODEL];
static __device__ float g_K[(size_t)MROWS * KVD];
static __device__ float g_V[(size_t)MROWS * KVD];
static __device__ float g_A[(size_t)MROWS * DMODEL];

// ---------------------------------------------------------------------------
// tf32 helpers
// ---------------------------------------------------------------------------
__device__ __forceinline__ uint32_t f2tf32(float x) {
    uint32_t u;
    asm("cvt.rna.tf32.f32 %0, %1;" : "=r"(u) : "r"(__float_as_uint(x)));
    return u;
}

__device__ __forceinline__ void mma_tf32(float c[4],
                                         uint32_t a0, uint32_t a1,
                                         uint32_t a2, uint32_t a3,
                                         uint32_t b0, uint32_t b1) {
    asm volatile(
        "mma.sync.aligned.m16n8k8.row.col.f32.tf32.tf32.f32 "
        "{%0,%1,%2,%3}, {%4,%5,%6,%7}, {%8,%9}, {%0,%1,%2,%3};"
        : "+f"(c[0]), "+f"(c[1]), "+f"(c[2]), "+f"(c[3])
        : "r"(a0), "r"(a1), "r"(a2), "r"(a3), "r"(b0), "r"(b1));
}

// GEMM smem swizzle (proven in R6)
__device__ __forceinline__ int gswz(int row, int col) {
    return (row << 5) + (col ^ ((row & 3) << 3));
}

// ---------------------------------------------------------------------------
// C[M,N] = A[M,K] @ W[N,K]^T via tf32 mma (unchanged from R6 — measured fast)
// ---------------------------------------------------------------------------
__global__ __launch_bounds__(256) void gemm_nt_tc_kernel(
    const float* __restrict__ A, const float* __restrict__ W,
    float* __restrict__ C, int M, int N, int K)
{
    __shared__ uint32_t As[128 * 32];
    __shared__ uint32_t Bs[128 * 32];

    const int tid  = threadIdx.x;
    const int lane = tid & 31;
    const int warp = tid >> 5;
    const int wm   = warp >> 1;
    const int wn   = warp & 1;
    const int g    = lane >> 2;
    const int t    = lane & 3;

    const int m0 = blockIdx.y * 128;
    const int n0 = blockIdx.x * 128;

    const int lrow = tid >> 3;
    const int lc4  = (tid & 7) << 2;

    float acc[2][8][4];
#pragma unroll
    for (int mt = 0; mt < 2; mt++)
#pragma unroll
        for (int nt = 0; nt < 8; nt++)
#pragma unroll
            for (int i = 0; i < 4; i++) acc[mt][nt][i] = 0.f;

#pragma unroll
    for (int it = 0; it < 4; it++) {
        const int row = lrow + it * 32;
        const float4 va = *(const float4*)&A[(size_t)(m0 + row) * K + lc4];
        const float4 vb = *(const float4*)&W[(size_t)(n0 + row) * K + lc4];
        uint32_t* da = &As[gswz(row, lc4)];
        uint32_t* db = &Bs[gswz(row, lc4)];
        da[0] = f2tf32(va.x); da[1] = f2tf32(va.y);
        da[2] = f2tf32(va.z); da[3] = f2tf32(va.w);
        db[0] = f2tf32(vb.x); db[1] = f2tf32(vb.y);
        db[2] = f2tf32(vb.z); db[3] = f2tf32(vb.w);
    }
    __syncthreads();

    for (int k0 = 0; k0 < K; k0 += 32) {
        const bool have_next = (k0 + 32) < K;

        float4 pa[4], pb[4];
        if (have_next) {
            const int kn = k0 + 32;
#pragma unroll
            for (int it = 0; it < 4; it++) {
                const int row = lrow + it * 32;
                pa[it] = *(const float4*)&A[(size_t)(m0 + row) * K + kn + lc4];
                pb[it] = *(const float4*)&W[(size_t)(n0 + row) * K + kn + lc4];
            }
        }

#pragma unroll
        for (int ks = 0; ks < 4; ks++) {
            const int kb = ks * 8 + 2 * t;
            uint2 af[2][2];
#pragma unroll
            for (int mt = 0; mt < 2; mt++) {
                const int ra = wm * 32 + mt * 16 + g;
                af[mt][0] = *(const uint2*)&As[gswz(ra,     kb)];
                af[mt][1] = *(const uint2*)&As[gswz(ra + 8, kb)];
            }
            uint2 bf[8];
#pragma unroll
            for (int nt = 0; nt < 8; nt++) {
                const int rb = wn * 64 + nt * 8 + g;
                bf[nt] = *(const uint2*)&Bs[gswz(rb, kb)];
            }
#pragma unroll
            for (int mt = 0; mt < 2; mt++)
#pragma unroll
                for (int nt = 0; nt < 8; nt++)
                    mma_tf32(acc[mt][nt],
                             af[mt][0].x, af[mt][1].x,
                             af[mt][0].y, af[mt][1].y,
                             bf[nt].x, bf[nt].y);
        }
        __syncthreads();

        if (have_next) {
#pragma unroll
            for (int it = 0; it < 4; it++) {
                const int row = lrow + it * 32;
                uint32_t* da = &As[gswz(row, lc4)];
                uint32_t* db = &Bs[gswz(row, lc4)];
                da[0] = f2tf32(pa[it].x); da[1] = f2tf32(pa[it].y);
                da[2] = f2tf32(pa[it].z); da[3] = f2tf32(pa[it].w);
                db[0] = f2tf32(pb[it].x); db[1] = f2tf32(pb[it].y);
                db[2] = f2tf32(pb[it].z); db[3] = f2tf32(pb[it].w);
            }
            __syncthreads();
        }
    }

#pragma unroll
    for (int mt = 0; mt < 2; mt++) {
        const int row = m0 + wm * 32 + mt * 16 + g;
#pragma unroll
        for (int nt = 0; nt < 8; nt++) {
            const int col = n0 + wn * 64 + nt * 8 + 2 * t;
            *(float2*)&C[(size_t)row * N + col] =
                make_float2(acc[mt][nt][0], acc[mt][nt][1]);
            *(float2*)&C[(size_t)(row + 8) * N + col] =
                make_float2(acc[mt][nt][2], acc[mt][nt][3]);
        }
    }
}

// ---------------------------------------------------------------------------
// Tensor-core causal GQA flash attention.
// CTA: 128 threads (4 warps); 64 query rows per CTA (16 per warp); 32-key
// tiles. QK^T and P@V both via tf32 mma; k-slot permutation makes the
// QK C-fragment coincide with the PV A-fragment (P never leaves registers).
// K in smem (pad 72), V transposed in smem (swizzled stride 40).
// ---------------------------------------------------------------------------
#define KS_STRIDE 72
#define VT_STRIDE 40
__device__ __forceinline__ int vt_off(int dim, int key) {
    return dim * VT_STRIDE + (key ^ ((dim >> 1) & 30));
}

__global__ __launch_bounds__(128) void attn_tc_kernel(
    const float* __restrict__ Q, const float* __restrict__ K,
    const float* __restrict__ V, float* __restrict__ O)
{
    __shared__ uint32_t Ks[32 * KS_STRIDE];   // [key][dim] tf32, pad 72
    __shared__ uint32_t Vt[64 * VT_STRIDE];   // [dim][key] tf32, swizzled

    const int qt   = gridDim.x - 1 - blockIdx.x;  // heavy CTAs first
    const int h    = blockIdx.y;
    const int b    = blockIdx.z;
    const int hk   = h >> 2;                      // GQA ratio 4
    const int tid  = threadIdx.x;
    const int lane = tid & 31;
    const int warp = tid >> 5;
    const int g    = lane >> 2;                   // mma group (row)
    const int t    = lane & 3;                    // thread-in-group

    const int qbase = qt * 64 + warp * 16;
    const int row0  = qbase + g;                  // query rows this lane owns
    const int row1  = qbase + g + 8;
    const float scale = 0.125f;                   // 1/sqrt(64)
    const float NEG_INF = -__int_as_float(0x7f800000);

    // --- Q fragments (loaded once): 8 k-steps x 4 regs, permuted k-slots ---
    uint32_t qf[8][4];   // [ks][a0=r0 k2t, a1=r1 k2t, a2=r0 k2t+1, a3=r1 k2t+1]
    {
        const float* q0p = Q + ((size_t)(b * SEQ + row0)) * DMODEL + h * HD;
        const float* q1p = Q + ((size_t)(b * SEQ + row1)) * DMODEL + h * HD;
#pragma unroll
        for (int ks = 0; ks < 8; ks++) {
            const float2 v0 = *(const float2*)(q0p + ks * 8 + 2 * t);
            const float2 v1 = *(const float2*)(q1p + ks * 8 + 2 * t);
            qf[ks][0] = f2tf32(v0.x); qf[ks][2] = f2tf32(v0.y);
            qf[ks][1] = f2tf32(v1.x); qf[ks][3] = f2tf32(v1.y);
        }
    }

    float acc_o[8][4];   // [dim-tile][c]: c0/c1 row0 dims 2t/2t+1, c2/c3 row1
#pragma unroll
    for (int nt = 0; nt < 8; nt++)
#pragma unroll
        for (int i = 0; i < 4; i++) acc_o[nt][i] = 0.f;
    float m0 = NEG_INF, m1 = NEG_INF, l0 = 0.f, l1 = 0.f;

    // Cooperative loader coords: 4 iters x (key = idx>>4, c4 = (idx&15)*4)
    const int kv_end = qt * 64 + 64;
    const int warp_lastj = qbase + 15;

    // --- prologue: tile 0 ---
#pragma unroll
    for (int it = 0; it < 4; it++) {
        const int idx = tid + it * 128;
        const int key = idx >> 4;
        const int c4  = (idx & 15) << 2;
        const size_t gro = ((size_t)(b * SEQ + key)) * KVD + hk * HD + c4;
        const float4 kv = *(const float4*)&K[gro];
        const float4 vv = *(const float4*)&V[gro];
        uint32_t* dk = &Ks[key * KS_STRIDE + c4];
        dk[0] = f2tf32(kv.x); dk[1] = f2tf32(kv.y);
        dk[2] = f2tf32(kv.z); dk[3] = f2tf32(kv.w);
        Vt[vt_off(c4 + 0, key)] = f2tf32(vv.x);
        Vt[vt_off(c4 + 1, key)] = f2tf32(vv.y);
        Vt[vt_off(c4 + 2, key)] = f2tf32(vv.z);
        Vt[vt_off(c4 + 3, key)] = f2tf32(vv.w);
    }
    __syncthreads();

    for (int j0 = 0; j0 < kv_end; j0 += 32) {
        const bool have_next = (j0 + 32) < kv_end;

        float4 pk[4], pv[4];
        if (have_next) {
#pragma unroll
            for (int it = 0; it < 4; it++) {
                const int idx = tid + it * 128;
                const int key = idx >> 4;
                const int c4  = (idx & 15) << 2;
                const size_t gro = ((size_t)(b * SEQ + j0 + 32 + key)) * KVD + hk * HD + c4;
                pk[it] = *(const float4*)&K[gro];
                pv[it] = *(const float4*)&V[gro];
            }
        }

        if (j0 <= warp_lastj) {   // causal: this warp has live rows in tile
            // ---- S = Q K^T (16 x 32) ----
            float s[4][4];
#pragma unroll
            for (int nt = 0; nt < 4; nt++)
#pragma unroll
                for (int i = 0; i < 4; i++) s[nt][i] = 0.f;

#pragma unroll
            for (int ks = 0; ks < 8; ks++) {
                uint2 bf[4];
#pragma unroll
                for (int nt = 0; nt < 4; nt++)
                    bf[nt] = *(const uint2*)&Ks[(nt * 8 + g) * KS_STRIDE + ks * 8 + 2 * t];
#pragma unroll
                for (int nt = 0; nt < 4; nt++)
                    mma_tf32(s[nt], qf[ks][0], qf[ks][1], qf[ks][2], qf[ks][3],
                             bf[nt].x, bf[nt].y);
            }

            // ---- scale + causal mask ----
            const bool need_mask = (j0 + 31 > qbase);
#pragma unroll
            for (int nt = 0; nt < 4; nt++) {
#pragma unroll
                for (int i = 0; i < 4; i++) {
                    float v = s[nt][i] * scale;
                    if (need_mask) {
                        const int col = j0 + nt * 8 + 2 * t + (i & 1);
                        const int row = (i < 2) ? row0 : row1;
                        if (col > row) v = NEG_INF;
                    }
                    s[nt][i] = v;
                }
            }

            // ---- row max (local 8 cols, then t-group shfl) ----
            float tm0 = NEG_INF, tm1 = NEG_INF;
#pragma unroll
            for (int nt = 0; nt < 4; nt++) {
                tm0 = fmaxf(tm0, fmaxf(s[nt][0], s[nt][1]));
                tm1 = fmaxf(tm1, fmaxf(s[nt][2], s[nt][3]));
            }
            tm0 = fmaxf(tm0, __shfl_xor_sync(0xffffffffu, tm0, 1));
            tm0 = fmaxf(tm0, __shfl_xor_sync(0xffffffffu, tm0, 2));
            tm1 = fmaxf(tm1, __shfl_xor_sync(0xffffffffu, tm1, 1));
            tm1 = fmaxf(tm1, __shfl_xor_sync(0xffffffffu, tm1, 2));

            const float mn0 = fmaxf(m0, tm0);
            const float mn1 = fmaxf(m1, tm1);
            const float c0 = __expf(m0 - mn0);
            const float c1 = __expf(m1 - mn1);
#pragma unroll
            for (int nt = 0; nt < 8; nt++) {
                acc_o[nt][0] *= c0; acc_o[nt][1] *= c0;
                acc_o[nt][2] *= c1; acc_o[nt][3] *= c1;
            }

            // ---- P = exp(s - m), l-sum, cvt to tf32 (stays in regs) ----
            uint32_t pf[4][4];
            float ls0 = 0.f, ls1 = 0.f;
#pragma unroll
            for (int nt = 0; nt < 4; nt++) {
                const float p0 = __expf(s[nt][0] - mn0);
                const float p1 = __expf(s[nt][1] - mn0);
                const float p2 = __expf(s[nt][2] - mn1);
                const float p3 = __expf(s[nt][3] - mn1);
                ls0 += p0 + p1; ls1 += p2 + p3;
                pf[nt][0] = f2tf32(p0); pf[nt][1] = f2tf32(p1);
                pf[nt][2] = f2tf32(p2); pf[nt][3] = f2tf32(p3);
            }
            ls0 += __shfl_xor_sync(0xffffffffu, ls0, 1);
            ls0 += __shfl_xor_sync(0xffffffffu, ls0, 2);
            ls1 += __shfl_xor_sync(0xffffffffu, ls1, 1);
            ls1 += __shfl_xor_sync(0xffffffffu, ls1, 2);
            l0 = l0 * c0 + ls0;
            l1 = l1 * c1 + ls1;
            m0 = mn0; m1 = mn1;

            // ---- O += P V : A-fragment of key-step kp == C-fragment pf[kp] ----
            // a0 = P(r0, kp*8+2t) = pf[kp][0]; a1 = P(r1, ..) = pf[kp][2];
            // a2 = P(r0, kp*8+2t+1) = pf[kp][1]; a3 = pf[kp][3].
#pragma unroll
            for (int kp = 0; kp < 4; kp++) {
#pragma unroll
                for (int nt = 0; nt < 8; nt++) {
                    const uint2 bv = *(const uint2*)&Vt[vt_off(nt * 8 + g, kp * 8 + 2 * t)];
                    mma_tf32(acc_o[nt], pf[kp][0], pf[kp][2], pf[kp][1], pf[kp][3],
                             bv.x, bv.y);
                }
            }
        }
        __syncthreads();

        if (have_next) {
#pragma unroll
            for (int it = 0; it < 4; it++) {
                const int idx = tid + it * 128;
                const int key = idx >> 4;
                const int c4  = (idx & 15) << 2;
                uint32_t* dk = &Ks[key * KS_STRIDE + c4];
                dk[0] = f2tf32(pk[it].x); dk[1] = f2tf32(pk[it].y);
                dk[2] = f2tf32(pk[it].z); dk[3] = f2tf32(pk[it].w);
                Vt[vt_off(c4 + 0, key)] = f2tf32(pv[it].x);
                Vt[vt_off(c4 + 1, key)] = f2tf32(pv[it].y);
                Vt[vt_off(c4 + 2, key)] = f2tf32(pv[it].z);
                Vt[vt_off(c4 + 3, key)] = f2tf32(pv[it].w);
            }
            __syncthreads();
        }
    }

    // ---- epilogue ----
    const float i0 = 1.f / l0;
    const float i1 = 1.f / l1;
    float* o0 = O + ((size_t)(b * SEQ + row0)) * DMODEL + h * HD;
    float* o1 = O + ((size_t)(b * SEQ + row1)) * DMODEL + h * HD;
#pragma unroll
    for (int nt = 0; nt < 8; nt++) {
        const int d = nt * 8 + 2 * t;
        *(float2*)(o0 + d) = make_float2(acc_o[nt][0] * i0, acc_o[nt][1] * i0);
        *(float2*)(o1 + d) = make_float2(acc_o[nt][2] * i1, acc_o[nt][3] * i1);
    }
}

// ---------------------------------------------------------------------------
extern "C" void kernel_launch(void* const* d_in, const int* in_sizes, int n_in,
                              void* d_out, int out_size)
{
    const float* x  = (const float*)d_in[0];
    const float* wq = (const float*)d_in[1];
    const float* wk = (const float*)d_in[2];
    const float* wv = (const float*)d_in[3];
    const float* wo = (const float*)d_in[4];
    float* out = (float*)d_out;

    float *Qp, *Kp, *Vp, *Ap;
    cudaGetSymbolAddress((void**)&Qp, g_Q);
    cudaGetSymbolAddress((void**)&Kp, g_K);
    cudaGetSymbolAddress((void**)&Vp, g_V);
    cudaGetSymbolAddress((void**)&Ap, g_A);

    // Projections (tf32 tensor core)
    gemm_nt_tc_kernel<<<dim3(DMODEL / 128, MROWS / 128), 256>>>(x, wq, Qp, MROWS, DMODEL, DMODEL);
    gemm_nt_tc_kernel<<<dim3(KVD / 128,    MROWS / 128), 256>>>(x, wk, Kp, MROWS, KVD,    DMODEL);
    gemm_nt_tc_kernel<<<dim3(KVD / 128,    MROWS / 128), 256>>>(x, wv, Vp, MROWS, KVD,    DMODEL);

    // Tensor-core causal GQA flash attention
    attn_tc_kernel<<<dim3(SEQ / 64, NH, BATCH), 128>>>(Qp, Kp, Vp, Ap);

    // Output projection (tf32 tensor core)
    gemm_nt_tc_kernel<<<dim3(DMODEL / 128, MROWS / 128), 256>>>(Ap, wo, out, MROWS, DMODEL, DMODEL);
}